// round 14
// baseline (speedup 1.0000x reference)
#include <cuda_runtime.h>
#include <math.h>

#define C_CLASSES 10000
#define K_PROTO   4
#define D_DIM     2048
#define N_PROTO   (C_CLASSES * K_PROTO)   // 40000
#define WARPS_PER_BLOCK 8
#define BLOCK1 (WARPS_PER_BLOCK * 32)     // 256
#define NTILES (N_PROTO / WARPS_PER_BLOCK)// 5000 streaming blocks
#define GRID (NTILES + 1)                 // +1 watcher block (block 0)

// scratch (no cudaMalloc allowed). Partials fully overwritten each run; the
// watcher resets g_done after reading -> graph-replay deterministic.
__device__ float g_pmin[NTILES];
__device__ float g_psum[NTILES];
__device__ float g_lbl[K_PROTO];
__device__ unsigned int g_done = 0;

__global__ __launch_bounds__(BLOCK1) void fused_kernel(
    const float* __restrict__ proto, const float* __restrict__ feat,
    const int* __restrict__ label, float* __restrict__ out) {
    const int tid  = threadIdx.x;
    const int lane = tid & 31;
    const int warp = tid >> 5;

    // ================= watcher block: merge when all partials arrive ========
    if (blockIdx.x == 0) {
        __shared__ float red[BLOCK1];
        if (tid == 0) {
            unsigned int v;
            do {
                asm volatile("ld.acquire.gpu.global.u32 %0, [%1];"
                             : "=r"(v) : "l"(&g_done) : "memory");
                if (v >= NTILES) break;
                __nanosleep(128);
            } while (true);
        }
        __syncthreads();   // acquire result visible block-wide

        // pass 1: gmin (independent loads)
        float m = INFINITY;
        for (int i = tid; i < NTILES; i += BLOCK1) m = fminf(m, g_pmin[i]);
        red[tid] = m;
        __syncthreads();
#pragma unroll
        for (int s = BLOCK1 / 2; s > 0; s >>= 1) {
            if (tid < s) red[tid] = fminf(red[tid], red[tid + s]);
            __syncthreads();
        }
        const float gmin = red[0];
        __syncthreads();

        // pass 2: total = sum_b s_b * exp(gmin - m_b) (independent terms)
        float sum = 0.0f;
        for (int i = tid; i < NTILES; i += BLOCK1)
            sum += g_psum[i] * __expf(gmin - g_pmin[i]);
        red[tid] = sum;
        __syncthreads();
#pragma unroll
        for (int s = BLOCK1 / 2; s > 0; s >>= 1) {
            if (tid < s) red[tid] += red[tid + s];
            __syncthreads();
        }

        if (tid == 0) {
            const float log_one = -gmin + logf(red[0]);
            float prob = 0.0f;
#pragma unroll
            for (int k = 0; k < K_PROTO; ++k)
                prob += log_one + g_lbl[k];   // log_one - logits
            out[0] = prob;
            g_done = 0;                        // reset for next graph replay
        }
        return;
    }

    // ================= streaming blocks (R4 engine, unchanged) ==============
    __shared__ float4 sf[D_DIM / 4];   // 8 KB feature tile
    __shared__ float  wdist[WARPS_PER_BLOCK];

    const float4* __restrict__ f4 = reinterpret_cast<const float4*>(feat);
    for (int i = tid; i < D_DIM / 4; i += BLOCK1) sf[i] = f4[i];
    __syncthreads();

    const int b = blockIdx.x - 1;
    const int p = b * WARPS_PER_BLOCK + warp;
    const float4* __restrict__ pp =
        reinterpret_cast<const float4*>(proto + (size_t)p * D_DIM);
    float acc = 0.0f;
#pragma unroll
    for (int i = 0; i < 16; ++i) {     // 16 float4 per lane = 2048/(32*4)
        float4 v = __ldcs(pp + lane + i * 32);   // read-once data
        float4 f = sf[lane + i * 32];
        float dx = v.x - f.x;
        float dy = v.y - f.y;
        float dz = v.z - f.z;
        float dw = v.w - f.w;
        acc += dx * dx + dy * dy + dz * dz + dw * dw;
    }
#pragma unroll
    for (int o = 16; o > 0; o >>= 1)
        acc += __shfl_xor_sync(0xFFFFFFFFu, acc, o);

    if (lane == 0) {
        wdist[warp] = acc;
        if ((p >> 2) == *label) {      // rare: exactly one block takes this
            g_lbl[p & 3] = acc;
            __threadfence();           // order g_lbl before this block's RED
        }
    }
    __syncthreads();

    // block partial (m, s): warp 0 lanes 0..7; then fire-and-forget ticket
    if (warp == 0) {
        float d = (lane < WARPS_PER_BLOCK) ? wdist[lane] : INFINITY;
        float m = d;
#pragma unroll
        for (int o = 4; o > 0; o >>= 1)
            m = fminf(m, __shfl_xor_sync(0xFFu, m, o, 8));
        float e = (lane < WARPS_PER_BLOCK) ? __expf(m - d) : 0.0f;
#pragma unroll
        for (int o = 4; o > 0; o >>= 1)
            e += __shfl_xor_sync(0xFFu, e, o, 8);
        if (lane == 0) {
            g_pmin[b] = m;
            g_psum[b] = e;
            // release-RED: orders the stores above, returns nothing -> no
            // round-trip, block retires immediately.
            asm volatile("red.release.gpu.global.add.u32 [%0], 1;"
                         :: "l"(&g_done) : "memory");
        }
    }
}

extern "C" void kernel_launch(void* const* d_in, const int* in_sizes, int n_in,
                              void* d_out, int out_size) {
    const float* feature = (const float*)d_in[0];
    const int*   label   = (const int*)d_in[1];
    const float* protos  = (const float*)d_in[2];
    float* out = (float*)d_out;

    fused_kernel<<<GRID, BLOCK1>>>(protos, feature, label, out);
}

// round 16
// speedup vs baseline: 1.1014x; 1.1014x over previous
#include <cuda_runtime.h>
#include <math.h>

#define C_CLASSES 10000
#define K_PROTO   4
#define D_DIM     2048
#define N_PROTO   (C_CLASSES * K_PROTO)    // 40000
#define WARPS_PER_BLOCK 8
#define BLOCK1 (WARPS_PER_BLOCK * 32)      // 256
#define NTILES (N_PROTO / WARPS_PER_BLOCK) // 5000 streaming blocks
#define GRID (NTILES + 1)                  // +1 watcher block (block 0)

// scratch (no cudaMalloc allowed). Zero = "not yet written" sentinel:
//  - g_pair slot valid iff high 32 bits (s) != 0, since s >= 1 always.
//  - g_lbl_enc[k] = ~bits(d): never 0 for finite d >= 0.
// Watcher resets everything to 0 before exiting -> graph-replay deterministic
// (zero-init statics also cover the very first run).
__device__ unsigned long long g_pair[NTILES];
__device__ unsigned int g_lbl_enc[K_PROTO];

__global__ __launch_bounds__(BLOCK1) void fused_kernel(
    const float* __restrict__ proto, const float* __restrict__ feat,
    const int* __restrict__ label, float* __restrict__ out) {
    const int tid  = threadIdx.x;
    const int lane = tid & 31;
    const int warp = tid >> 5;

    // ============ watcher block 0: consume partials as they appear ==========
    if (blockIdx.x == 0) {
        __shared__ float rm[BLOCK1], rs[BLOCK1];
        volatile unsigned long long* vp =
            (volatile unsigned long long*)g_pair;

        float m = INFINITY, s = 0.0f;
        for (int i = tid; i < NTILES; i += BLOCK1) {
            unsigned long long v = vp[i];
            while ((unsigned int)(v >> 32) == 0u) {   // s==0 -> not written
                __nanosleep(64);
                v = vp[i];
            }
            float pm = __uint_as_float((unsigned int)v);
            float ps = __uint_as_float((unsigned int)(v >> 32));
            float nm = fminf(m, pm);
            s = s * __expf(nm - m) + ps * __expf(nm - pm);
            m = nm;
        }
        rm[tid] = m; rs[tid] = s;
        __syncthreads();
#pragma unroll
        for (int step = BLOCK1 / 2; step > 0; step >>= 1) {
            if (tid < step) {
                float m1 = rm[tid], s1 = rs[tid];
                float m2 = rm[tid + step], s2 = rs[tid + step];
                float nm = fminf(m1, m2);
                rm[tid] = nm;
                rs[tid] = s1 * __expf(nm - m1) + s2 * __expf(nm - m2);
            }
            __syncthreads();
        }

        if (tid == 0) {
            // label distances (poll: encoded value never 0 once written)
            volatile unsigned int* vl = (volatile unsigned int*)g_lbl_enc;
            float prob = 0.0f;
            const float log_one = -rm[0] + logf(rs[0]);
#pragma unroll
            for (int k = 0; k < K_PROTO; ++k) {
                unsigned int e = vl[k];
                while (e == 0u) { __nanosleep(64); e = vl[k]; }
                prob += log_one + __uint_as_float(~e);
            }
            out[0] = prob;
        }
        __syncthreads();
        // reset sentinels for the next graph replay (visible at kernel end)
        for (int i = tid; i < NTILES; i += BLOCK1) g_pair[i] = 0ull;
        if (tid < K_PROTO) g_lbl_enc[tid] = 0u;
        return;
    }

    // ============ streaming blocks: R4 engine, weak stores only =============
    __shared__ float4 sf[D_DIM / 4];   // 8 KB feature tile
    __shared__ float  wdist[WARPS_PER_BLOCK];

    const float4* __restrict__ f4 = reinterpret_cast<const float4*>(feat);
    for (int i = tid; i < D_DIM / 4; i += BLOCK1) sf[i] = f4[i];
    __syncthreads();

    const int b = blockIdx.x - 1;
    const int p = b * WARPS_PER_BLOCK + warp;
    const float4* __restrict__ pp =
        reinterpret_cast<const float4*>(proto + (size_t)p * D_DIM);
    float acc = 0.0f;
#pragma unroll
    for (int i = 0; i < 16; ++i) {     // 16 float4 per lane = 2048/(32*4)
        float4 v = __ldcs(pp + lane + i * 32);   // read-once data
        float4 f = sf[lane + i * 32];
        float dx = v.x - f.x;
        float dy = v.y - f.y;
        float dz = v.z - f.z;
        float dw = v.w - f.w;
        acc += dx * dx + dy * dy + dz * dz + dw * dw;
    }
#pragma unroll
    for (int o = 16; o > 0; o >>= 1)
        acc += __shfl_xor_sync(0xFFFFFFFFu, acc, o);

    if (lane == 0) {
        wdist[warp] = acc;
        if ((p >> 2) == *label)
            g_lbl_enc[p & 3] = ~__float_as_uint(acc);  // weak store, never 0
    }
    __syncthreads();

    // block partial (m, s) packed as one 64-bit weak store
    if (warp == 0) {
        float d = (lane < WARPS_PER_BLOCK) ? wdist[lane] : INFINITY;
        float m = d;
#pragma unroll
        for (int o = 4; o > 0; o >>= 1)
            m = fminf(m, __shfl_xor_sync(0xFFu, m, o, 8));
        float e = (lane < WARPS_PER_BLOCK) ? __expf(m - d) : 0.0f;
#pragma unroll
        for (int o = 4; o > 0; o >>= 1)
            e += __shfl_xor_sync(0xFFu, e, o, 8);
        if (lane == 0) {
            unsigned long long v =
                ((unsigned long long)__float_as_uint(e) << 32) |
                (unsigned long long)__float_as_uint(m);
            g_pair[b] = v;            // single STG.64, plain/weak
        }
    }
}

extern "C" void kernel_launch(void* const* d_in, const int* in_sizes, int n_in,
                              void* d_out, int out_size) {
    const float* feature = (const float*)d_in[0];
    const int*   label   = (const int*)d_in[1];
    const float* protos  = (const float*)d_in[2];
    float* out = (float*)d_out;

    fused_kernel<<<GRID, BLOCK1>>>(protos, feature, label, out);
}